// round 8
// baseline (speedup 1.0000x reference)
#include <cuda_runtime.h>

#define NP 512
#define NR 256
#define NS 256

// Order-preserving key: larger value wins; on value tie, LOWER index wins
// (matches jax.lax.top_k stable ordering). Key is always > 0 for finite floats.
__device__ __forceinline__ unsigned long long mk_key(float v, int idx) {
    unsigned u = __float_as_uint(v);
    u = (u & 0x80000000u) ? ~u : (u | 0x80000000u);
    return ((unsigned long long)u << 32) | (unsigned)(~(unsigned)idx);
}
__device__ __forceinline__ int key_idx(unsigned long long k) {
    return (int)(~(unsigned)k);   // recover original index from low 32 bits
}
// Insert key into descending top-3 triple (a >= b >= c).
__device__ __forceinline__ void ins3(unsigned long long k,
                                     unsigned long long &a,
                                     unsigned long long &b,
                                     unsigned long long &c) {
    if (k > c) {
        if (k > b) {
            c = b;
            if (k > a) { b = a; a = k; } else { b = k; }
        } else {
            c = k;
        }
    }
}

__global__ __launch_bounds__(256) void iapm_kernel(
    const float* __restrict__ score,
    const int* __restrict__ ref_mask,   // bool stored as 4-byte words (nonzero = true)
    const int* __restrict__ src_mask,
    float* __restrict__ out_score,
    float* __restrict__ out_corr)
{
    __shared__ int row_top[NR][3];   // top-3 s-indices per row
    __shared__ int col_top[NS][3];   // top-3 r-indices per column
    __shared__ unsigned char smr[NR];
    __shared__ unsigned char sms[NS];

    const int p    = blockIdx.x;
    const int tid  = threadIdx.x;
    const int lane = tid & 31;
    const int warp = tid >> 5;
    const float* base = score + (size_t)p * NR * NS;

    smr[tid] = (ref_mask[p * NR + tid] != 0) ? 1 : 0;
    sms[tid] = (src_mask[p * NS + tid] != 0) ? 1 : 0;

    // ---- Pass 1: per-row top-3 along s. Warp per row (coalesced DRAM read),
    //      8 warps x 32 rows each.
    for (int rr = warp * 32; rr < warp * 32 + 32; ++rr) {
        const float* row = base + rr * NS;
        unsigned long long a = 0ULL, b = 0ULL, c = 0ULL;
        #pragma unroll
        for (int j = 0; j < NS / 32; ++j) {
            int s = lane + j * 32;
            ins3(mk_key(row[s], s), a, b, c);
        }
        #pragma unroll
        for (int off = 16; off; off >>= 1) {
            unsigned long long oa = __shfl_down_sync(0xFFFFFFFFu, a, off);
            unsigned long long ob = __shfl_down_sync(0xFFFFFFFFu, b, off);
            unsigned long long oc = __shfl_down_sync(0xFFFFFFFFu, c, off);
            ins3(oa, a, b, c);
            ins3(ob, a, b, c);
            ins3(oc, a, b, c);
        }
        if (lane == 0) {
            row_top[rr][0] = key_idx(a);
            row_top[rr][1] = key_idx(b);
            row_top[rr][2] = key_idx(c);
        }
    }

    // ---- Pass 2: per-column top-3 along r. Thread per column; reads are
    //      coalesced across the warp and hit L2 (tile just streamed in).
    {
        unsigned long long a = 0ULL, b = 0ULL, c = 0ULL;
        for (int r = 0; r < NR; ++r)
            ins3(mk_key(base[r * NS + tid], r), a, b, c);
        col_top[tid][0] = key_idx(a);
        col_top[tid][1] = key_idx(b);
        col_top[tid][2] = key_idx(c);
    }
    __syncthreads();

    // ---- Pass 3: elementwise output. Thread tid owns column tid; iterate
    //      rows so both output writes are fully coalesced.
    const int   c0 = col_top[tid][0], c1 = col_top[tid][1], c2 = col_top[tid][2];
    const bool  ms = sms[tid] != 0;
    float* os = out_score + (size_t)p * NR * NS;
    float* oc = out_corr  + (size_t)p * NR * NS;

    for (int r = 0; r < NR; ++r) {
        float v = expf(base[r * NS + tid]);
        bool inr = (tid == row_top[r][0]) | (tid == row_top[r][1]) | (tid == row_top[r][2]);
        bool inc = (r == c0) | (r == c1) | (r == c2);
        float sc = 0.5f * ((inr ? v : 0.0f) + (inc ? v : 0.0f));
        bool cmask = (smr[r] != 0) && ms;
        bool corr  = ((inr && v > 0.0f) || (inc && v > 0.0f)) && cmask;
        os[r * NS + tid] = sc;
        oc[r * NS + tid] = corr ? 1.0f : 0.0f;
    }
}

extern "C" void kernel_launch(void* const* d_in, const int* in_sizes, int n_in,
                              void* d_out, int out_size) {
    // metadata order: matching_score_map [P,R,S] f32, node_corr_scores [P] f32 (unused),
    //                 ref_knn_masks [P,R] bool(4B words), src_knn_masks [P,S] bool(4B words)
    const float* score = (const float*)d_in[0];
    const int*   refm  = (const int*)d_in[2];
    const int*   srcm  = (const int*)d_in[3];

    float* out = (float*)d_out;
    size_t total = (size_t)NP * NR * NS;
    // Outputs concatenated as float32: [score_map, corr_map(bool->f32)]
    float* out_corr = out + total;

    iapm_kernel<<<NP, 256>>>(score, refm, srcm, out, out_corr);
}